// round 8
// baseline (speedup 1.0000x reference)
#include <cuda_runtime.h>
#include <cstdint>

// ---------------------------------------------------------------------------
// T=16384, D=H=2880, E=8, C=2048, N1=5760. K=2880 both GEMMs.
// mma.sync tf32, CTA tile 128x192, 8 warps (2M x 4N), warp tile 64x48.
// ldmatrix fragment loads + double-buffered k-step fragments (covers LDS
// latency with MMA work). 3-stage cp.async, 1 barrier per K-iter.
// A-side pre-rounded tf32 (x prepass; act rounded at GEMM1 epilogue);
// B-side (weights) raw with in-register cvt.rn.tf32.
// ---------------------------------------------------------------------------
#define KDIM 2880
#define BM 128
#define BN 192
#define NT 6
#define BK 32
#define NSTAGE 3
#define NKITER 90
#define LDSF 36
#define A_FLOATS (BM * LDSF)
#define B_FLOATS (BN * LDSF)
#define STAGE_FLOATS (A_FLOATS + B_FLOATS)
#define STAGE_BYTES (STAGE_FLOATS * 4)
#define SMEM_BYTES (NSTAGE * STAGE_BYTES)  // 138240
#define NTHR 256

__device__ float g_x[(size_t)16384 * 2880];
__device__ float g_act[(size_t)16384 * 2880];

__device__ __forceinline__ uint32_t s2u(const void* p) {
    uint32_t a;
    asm("{.reg .u64 t; cvta.to.shared.u64 t, %1; cvt.u32.u64 %0, t;}"
        : "=r"(a) : "l"(p));
    return a;
}
__device__ __forceinline__ float rtf32(float v) {
    uint32_t u;
    asm("cvt.rn.tf32.f32 %0, %1;" : "=r"(u) : "f"(v));
    return __uint_as_float(u);
}
__device__ __forceinline__ uint32_t f2tf32u(uint32_t raw) {
    uint32_t u;
    asm("cvt.rn.tf32.f32 %0, %1;" : "=r"(u) : "f"(__uint_as_float(raw)));
    return u;
}
__device__ __forceinline__ void cp16(uint32_t dst, const void* src) {
    asm volatile("cp.async.cg.shared.global [%0], [%1], 16;" ::"r"(dst),
                 "l"(src) : "memory");
}
__device__ __forceinline__ void ldsm_x4(uint32_t* r, uint32_t addr) {
    asm volatile(
        "ldmatrix.sync.aligned.m8n8.x4.shared.b16 {%0,%1,%2,%3}, [%4];"
        : "=r"(r[0]), "=r"(r[1]), "=r"(r[2]), "=r"(r[3]) : "r"(addr));
}
__device__ __forceinline__ void ldsm_x2(uint32_t* r, uint32_t addr) {
    asm volatile(
        "ldmatrix.sync.aligned.m8n8.x2.shared.b16 {%0,%1}, [%2];"
        : "=r"(r[0]), "=r"(r[1]) : "r"(addr));
}
__device__ __forceinline__ void mma_tf32(float* c, const uint32_t* a,
                                         const uint32_t* b) {
    asm volatile(
        "mma.sync.aligned.m16n8k8.row.col.f32.tf32.tf32.f32 "
        "{%0,%1,%2,%3}, {%4,%5,%6,%7}, {%8,%9}, {%0,%1,%2,%3};"
        : "+f"(c[0]), "+f"(c[1]), "+f"(c[2]), "+f"(c[3])
        : "r"(a[0]), "r"(a[1]), "r"(a[2]), "r"(a[3]), "r"(b[0]), "r"(b[1]));
}

__global__ void round_tf32_kernel(const float4* __restrict__ src,
                                  float4* __restrict__ dst, size_t n4) {
    size_t i = (size_t)blockIdx.x * blockDim.x + threadIdx.x;
    size_t stride = (size_t)gridDim.x * blockDim.x;
    for (; i < n4; i += stride) {
        float4 v = src[i];
        v.x = rtf32(v.x); v.y = rtf32(v.y);
        v.z = rtf32(v.z); v.w = rtf32(v.w);
        dst[i] = v;
    }
}

// ---------------------------------------------------------------------------
template <bool SWIGLU>
__global__ __launch_bounds__(NTHR, 1)
void moe_mma_kernel(const float* __restrict__ Bw, const float* __restrict__ bias,
                    float* __restrict__ Dout) {
    extern __shared__ float smem[];
    const uint32_t smem_u = s2u(smem);

    const int tid = threadIdx.x;
    const int lane = tid & 31;
    const int warp = tid >> 5;
    const int wm = warp & 1;   // 2 warps along M (64 rows)
    const int wn = warp >> 1;  // 4 warps along N (48 cols)

    const int bn = blockIdx.x, bm = blockIdx.y;
    const int e = bm >> 4;
    const size_t row0 = (size_t)bm * BM;
    const int n0 = bn * BN;
    const int NBROWS = SWIGLU ? 5760 : 2880;

    const float* Abase = (SWIGLU ? g_x : g_act) + row0 * KDIM;
    const float* Bbase = Bw + (size_t)e * NBROWS * KDIM + (size_t)n0 * KDIM;

    // copy map: (128+192) rows x 8 chunks = 2560 = 10 x 256. Branch-free.
    const int crb = tid >> 3;       // 0..31
    const int cc4 = (tid & 7) * 4;  // k-offset (floats)
    const float* Acp = Abase + (size_t)crb * KDIM + cc4;
    const float* Bcp = Bbase + (size_t)crb * KDIM + cc4;
    const uint32_t sAo = smem_u + (crb * LDSF + cc4) * 4;
    const uint32_t sBo = smem_u + (A_FLOATS + crb * LDSF + cc4) * 4;
    const size_t gstep = (size_t)32 * KDIM;

#pragma unroll
    for (int p = 0; p < NSTAGE - 1; p++) {
        const uint32_t sb = p * STAGE_BYTES;
        const int k0 = p * BK;
#pragma unroll
        for (int q = 0; q < 4; q++)
            cp16(sAo + sb + q * (32 * LDSF * 4), Acp + q * gstep + k0);
#pragma unroll
        for (int q = 0; q < 6; q++)
            cp16(sBo + sb + q * (32 * LDSF * 4), Bcp + q * gstep + k0);
        asm volatile("cp.async.commit_group;" ::: "memory");
    }

    float acc[4][NT][4];
#pragma unroll
    for (int i = 0; i < 4; i++)
#pragma unroll
        for (int j = 0; j < NT; j++)
#pragma unroll
            for (int k = 0; k < 4; k++) acc[i][j][k] = 0.0f;

    // ldmatrix per-lane byte offsets (within a stage)
    //  A: lanes 0-7 -> m rows 0-7 @k, 8-15 -> m8-15 @k, 16-23 -> m0-7 @k+4,
    //     24-31 -> m8-15 @k+4   (matches a0..a3 of m16n8k8)
    const uint32_t aOff =
        ((wm * 64 + (lane & 7) + ((lane >> 3) & 1) * 8) * LDSF +
         ((lane >> 4) & 1) * 4) * 4;
    //  B (x2): lanes 0-7 -> n rows @k, 8-15 -> n rows @k+4
    const uint32_t bOff =
        (A_FLOATS + (wn * 48 + (lane & 7)) * LDSF + ((lane >> 3) & 1) * 4) * 4;

    uint32_t af[2][4][4], bf[2][NT][2];

    for (int it = 0; it < NKITER; it++) {
        asm volatile("cp.async.wait_group 1;" ::: "memory");
        __syncthreads();

        const int kf = it + NSTAGE - 1;
        if (kf < NKITER) {
            const uint32_t sb = (kf % NSTAGE) * STAGE_BYTES;
            const int k0 = kf * BK;
#pragma unroll
            for (int q = 0; q < 4; q++)
                cp16(sAo + sb + q * (32 * LDSF * 4), Acp + q * gstep + k0);
#pragma unroll
            for (int q = 0; q < 6; q++)
                cp16(sBo + sb + q * (32 * LDSF * 4), Bcp + q * gstep + k0);
        }
        asm volatile("cp.async.commit_group;" ::: "memory");

        const uint32_t stA = smem_u + (it % NSTAGE) * STAGE_BYTES + aOff;
        const uint32_t stB = smem_u + (it % NSTAGE) * STAGE_BYTES + bOff;

        // load k-step 0 fragments into buffer 0
#pragma unroll
        for (int i = 0; i < 4; i++) ldsm_x4(af[0][i], stA + i * (16 * LDSF * 4));
#pragma unroll
        for (int j = 0; j < NT; j++) ldsm_x2(bf[0][j], stB + j * (8 * LDSF * 4));

#pragma unroll
        for (int kk8 = 0; kk8 < 4; kk8++) {
            const int cur = kk8 & 1;
            if (kk8 < 3) {  // prefetch next k-step fragments
                const uint32_t ka = stA + (kk8 + 1) * 32;  // 8 floats
                const uint32_t kb = stB + (kk8 + 1) * 32;
                const int nxt = cur ^ 1;
#pragma unroll
                for (int i = 0; i < 4; i++)
                    ldsm_x4(af[nxt][i], ka + i * (16 * LDSF * 4));
#pragma unroll
                for (int j = 0; j < NT; j++)
                    ldsm_x2(bf[nxt][j], kb + j * (8 * LDSF * 4));
            }
            // cvt B (weights are raw fp32) then MMA
            uint32_t bc[NT][2];
#pragma unroll
            for (int j = 0; j < NT; j++) {
                bc[j][0] = f2tf32u(bf[cur][j][0]);
                bc[j][1] = f2tf32u(bf[cur][j][1]);
            }
#pragma unroll
            for (int i = 0; i < 4; i++)
#pragma unroll
                for (int j = 0; j < NT; j++)
                    mma_tf32(acc[i][j], af[cur][i], bc[j]);
        }
    }

    // epilogue (register-resident; pairs (2q,2q+1) in c0/c1 and c2/c3)
    const int q2 = 2 * (lane & 3);
    if (SWIGLU) {
        const float* bb = bias + (size_t)e * NBROWS + n0 + wn * 48;
        float* actb = g_act + row0 * 2880 + (size_t)(n0 >> 1) + wn * 24;
        float2 bj[NT];
#pragma unroll
        for (int j = 0; j < NT; j++) bj[j] = *(const float2*)(bb + j * 8 + q2);
#pragma unroll
        for (int i = 0; i < 4; i++) {
            const int r1 = wm * 64 + i * 16 + (lane >> 2);
#pragma unroll
            for (int j = 0; j < NT; j++) {
                const int hc = j * 4 + (lane & 3);
#pragma unroll
                for (int hrow = 0; hrow < 2; hrow++) {
                    float g = acc[i][j][2 * hrow] + bj[j].x;
                    float l = acc[i][j][2 * hrow + 1] + bj[j].y;
                    g = fminf(g, 7.0f);
                    l = fminf(fmaxf(l, -7.0f), 7.0f);
                    float sg = 1.0f / (1.0f + __expf(-1.702f * g));
                    actb[(size_t)(r1 + 8 * hrow) * 2880 + hc] =
                        rtf32(g * sg * (l + 1.0f));
                }
            }
        }
    } else {
        const float* bb = bias + (size_t)e * NBROWS + n0 + wn * 48;
        float* ob = Dout + row0 * 2880 + n0 + wn * 48;
        float2 bj[NT];
#pragma unroll
        for (int j = 0; j < NT; j++) bj[j] = *(const float2*)(bb + j * 8 + q2);
#pragma unroll
        for (int i = 0; i < 4; i++) {
            const int r1 = wm * 64 + i * 16 + (lane >> 2);
#pragma unroll
            for (int j = 0; j < NT; j++) {
                const int oc = j * 8 + q2;
#pragma unroll
                for (int hrow = 0; hrow < 2; hrow++) {
                    float2 v;
                    v.x = acc[i][j][2 * hrow] + bj[j].x;
                    v.y = acc[i][j][2 * hrow + 1] + bj[j].y;
                    *(float2*)(ob + (size_t)(r1 + 8 * hrow) * 2880 + oc) = v;
                }
            }
        }
    }
}

// ---------------------------------------------------------------------------
extern "C" void kernel_launch(void* const* d_in, const int* in_sizes, int n_in,
                              void* d_out, int out_size) {
    const float* x = (const float*)d_in[0];
    const float* w1 = (const float*)d_in[2];
    const float* b1 = (const float*)d_in[3];
    const float* w2 = (const float*)d_in[4];
    const float* b2 = (const float*)d_in[5];
    float* out = (float*)d_out;

    cudaFuncSetAttribute(moe_mma_kernel<true>,
                         cudaFuncAttributeMaxDynamicSharedMemorySize, SMEM_BYTES);
    cudaFuncSetAttribute(moe_mma_kernel<false>,
                         cudaFuncAttributeMaxDynamicSharedMemorySize, SMEM_BYTES);

    float* gx;
    cudaGetSymbolAddress((void**)&gx, g_x);
    const size_t nx = (size_t)16384 * 2880 / 4;
    round_tf32_kernel<<<2048, 256>>>((const float4*)x, (float4*)gx, nx);

    // GEMM1: 5760/192 = 30 n-tiles; GEMM2: 2880/192 = 15 n-tiles
    moe_mma_kernel<true><<<dim3(30, 128), NTHR, SMEM_BYTES>>>(w1, b1, nullptr);
    moe_mma_kernel<false><<<dim3(15, 128), NTHR, SMEM_BYTES>>>(w2, b2, out);
}

// round 9
// speedup vs baseline: 1.8403x; 1.8403x over previous
#include <cuda_runtime.h>
#include <cuda_fp16.h>
#include <cstdint>

// ---------------------------------------------------------------------------
// T=16384, D=H=2880, E=8, C=2048, N1=5760. K=2880 both GEMMs.
// fp16 mma.sync m16n8k16 (fp32 accumulate): same 10-bit mantissa as tf32 at
// 2x the tensor rate, half the smem/L2/LDS traffic. All operands pre-
// converted to fp16 (x,w1,w2 via prepass; activations written fp16 by the
// GEMM1 epilogue). CTA 128x192, 8 warps (2Mx4N), warp tile 64x48, BK=64,
// 3-stage cp.async, 1 barrier/iter, ldmatrix frags + k-step double-buffer.
// ---------------------------------------------------------------------------
#define KDIM 2880
#define BM 128
#define BN 192
#define BK 64              // halves per k-stage
#define NT 6
#define NKITER 45          // 2880/64
#define NSTAGE 3
#define LDSH 72            // smem pitch in halves (64 + 8 pad) = 144B
#define A_BYTES (BM * LDSH * 2)                  // 18432
#define STAGE_BYTES ((BM + BN) * LDSH * 2)       // 46080
#define SMEM_BYTES (NSTAGE * STAGE_BYTES)        // 138240
#define NTHR 256

__device__ __half g_xh[(size_t)16384 * 2880];
__device__ __half g_w1h[(size_t)8 * 5760 * 2880];
__device__ __half g_w2h[(size_t)8 * 2880 * 2880];
__device__ __half g_acth[(size_t)16384 * 2880];

__device__ __forceinline__ uint32_t s2u(const void* p) {
    uint32_t a;
    asm("{.reg .u64 t; cvta.to.shared.u64 t, %1; cvt.u32.u64 %0, t;}"
        : "=r"(a) : "l"(p));
    return a;
}
__device__ __forceinline__ void cp16(uint32_t dst, const void* src) {
    asm volatile("cp.async.cg.shared.global [%0], [%1], 16;" ::"r"(dst),
                 "l"(src) : "memory");
}
__device__ __forceinline__ void ldsm_x4(uint32_t* r, uint32_t addr) {
    asm volatile(
        "ldmatrix.sync.aligned.m8n8.x4.shared.b16 {%0,%1,%2,%3}, [%4];"
        : "=r"(r[0]), "=r"(r[1]), "=r"(r[2]), "=r"(r[3]) : "r"(addr));
}
__device__ __forceinline__ void mma_f16(float* c, const uint32_t* a,
                                        const uint32_t* b) {
    asm volatile(
        "mma.sync.aligned.m16n8k16.row.col.f32.f16.f16.f32 "
        "{%0,%1,%2,%3}, {%4,%5,%6,%7}, {%8,%9}, {%0,%1,%2,%3};"
        : "+f"(c[0]), "+f"(c[1]), "+f"(c[2]), "+f"(c[3])
        : "r"(a[0]), "r"(a[1]), "r"(a[2]), "r"(a[3]), "r"(b[0]), "r"(b[1]));
}

// fp32 -> fp16 conversion prepass (grid-stride over float4)
__global__ void f32_to_f16_kernel(const float4* __restrict__ src,
                                  __half2* __restrict__ dst, size_t n4) {
    size_t i = (size_t)blockIdx.x * blockDim.x + threadIdx.x;
    size_t stride = (size_t)gridDim.x * blockDim.x;
    for (; i < n4; i += stride) {
        float4 v = src[i];
        dst[2 * i] = __floats2half2_rn(v.x, v.y);
        dst[2 * i + 1] = __floats2half2_rn(v.z, v.w);
    }
}

// ---------------------------------------------------------------------------
template <bool SWIGLU>
__global__ __launch_bounds__(NTHR, 1)
void moe_mma_kernel(const __half* __restrict__ Bw, const float* __restrict__ bias,
                    float* __restrict__ Dout) {
    extern __shared__ char smem[];
    const uint32_t smem_u = s2u(smem);

    const int tid = threadIdx.x;
    const int lane = tid & 31;
    const int warp = tid >> 5;
    const int wm = warp & 1;   // 2 warps along M (64 rows)
    const int wn = warp >> 1;  // 4 warps along N (48 cols)

    const int bn = blockIdx.x, bm = blockIdx.y;
    const int e = bm >> 4;     // 16 m-tiles per expert
    const size_t row0 = (size_t)bm * BM;
    const int n0 = bn * BN;
    const int NBROWS = SWIGLU ? 5760 : 2880;

    const __half* Abase = (SWIGLU ? g_xh : g_acth) + row0 * KDIM;
    const __half* Bbase = Bw + (size_t)e * NBROWS * KDIM + (size_t)n0 * KDIM;

    // copy map: 320 rows x 8 chunks(16B) = 2560 = 10 x 256. Branch-free.
    const int crb = tid >> 3;        // row within 32-row group
    const int cc8 = (tid & 7) * 8;   // k-offset in halves (16B chunks)
    const __half* Acp = Abase + (size_t)crb * KDIM + cc8;
    const __half* Bcp = Bbase + (size_t)crb * KDIM + cc8;
    const uint32_t sAo = smem_u + (crb * LDSH + cc8) * 2;
    const uint32_t sBo = smem_u + A_BYTES + (crb * LDSH + cc8) * 2;
    const size_t gstep = (size_t)32 * KDIM;
    const uint32_t sstep = 32 * LDSH * 2;

#pragma unroll
    for (int p = 0; p < NSTAGE - 1; p++) {
        const uint32_t sb = p * STAGE_BYTES;
        const int k0 = p * BK;
#pragma unroll
        for (int q = 0; q < 4; q++)
            cp16(sAo + sb + q * sstep, Acp + q * gstep + k0);
#pragma unroll
        for (int q = 0; q < 6; q++)
            cp16(sBo + sb + q * sstep, Bcp + q * gstep + k0);
        asm volatile("cp.async.commit_group;" ::: "memory");
    }

    float acc[4][NT][4];
#pragma unroll
    for (int i = 0; i < 4; i++)
#pragma unroll
        for (int j = 0; j < NT; j++)
#pragma unroll
            for (int k = 0; k < 4; k++) acc[i][j][k] = 0.0f;

    // ldmatrix lane->address maps (byte offsets within a stage)
    // A x4: matrices (m0-7@k0),(m8-15@k0),(m0-7@k8),(m8-15@k8)
    const uint32_t aOff =
        ((wm * 64 + (lane & 15)) * LDSH + (lane >> 4) * 8) * 2;
    // B x4 (two n8 frags): (n0-7@k0),(n0-7@k8),(n8-15@k0),(n8-15@k8)
    const uint32_t bOff =
        A_BYTES +
        ((wn * 48 + (lane & 7) + ((lane >> 4) & 1) * 8) * LDSH +
         ((lane >> 3) & 1) * 8) * 2;

    uint32_t af[2][4][4], bf[2][3][4];

    for (int it = 0; it < NKITER; it++) {
        asm volatile("cp.async.wait_group 1;" ::: "memory");
        __syncthreads();

        const int kf = it + NSTAGE - 1;
        if (kf < NKITER) {
            const uint32_t sb = (kf % NSTAGE) * STAGE_BYTES;
            const int k0 = kf * BK;
#pragma unroll
            for (int q = 0; q < 4; q++)
                cp16(sAo + sb + q * sstep, Acp + q * gstep + k0);
#pragma unroll
            for (int q = 0; q < 6; q++)
                cp16(sBo + sb + q * sstep, Bcp + q * gstep + k0);
        }
        asm volatile("cp.async.commit_group;" ::: "memory");

        const uint32_t stg = smem_u + (it % NSTAGE) * STAGE_BYTES;
        const uint32_t stA = stg + aOff;
        const uint32_t stB = stg + bOff;

        // k-step 0 fragments -> buffer 0  (k-step = 16 halves = 32 bytes)
#pragma unroll
        for (int i = 0; i < 4; i++)
            ldsm_x4(af[0][i], stA + i * (16 * LDSH * 2));
#pragma unroll
        for (int p = 0; p < 3; p++)
            ldsm_x4(bf[0][p], stB + p * (16 * LDSH * 2));

#pragma unroll
        for (int kk = 0; kk < 4; kk++) {  // 4 k16-steps per BK=64
            const int cur = kk & 1;
            if (kk < 3) {
                const int nxt = cur ^ 1;
                const uint32_t ka = stA + (kk + 1) * 32;
                const uint32_t kb = stB + (kk + 1) * 32;
#pragma unroll
                for (int i = 0; i < 4; i++)
                    ldsm_x4(af[nxt][i], ka + i * (16 * LDSH * 2));
#pragma unroll
                for (int p = 0; p < 3; p++)
                    ldsm_x4(bf[nxt][p], kb + p * (16 * LDSH * 2));
            }
#pragma unroll
            for (int i = 0; i < 4; i++)
#pragma unroll
                for (int j = 0; j < NT; j++)
                    mma_f16(acc[i][j], af[cur][i], bf[cur][j >> 1] + (j & 1) * 2);
        }
    }

    // epilogue (register-resident; pairs (2q,2q+1) in c0/c1 and c2/c3)
    const int q2 = 2 * (lane & 3);
    if (SWIGLU) {
        const float* bb = bias + (size_t)e * NBROWS + n0 + wn * 48;
        __half* actb = g_acth + row0 * 2880 + (size_t)(n0 >> 1) + wn * 24;
        float2 bj[NT];
#pragma unroll
        for (int j = 0; j < NT; j++) bj[j] = *(const float2*)(bb + j * 8 + q2);
#pragma unroll
        for (int i = 0; i < 4; i++) {
            const int r1 = wm * 64 + i * 16 + (lane >> 2);
#pragma unroll
            for (int j = 0; j < NT; j++) {
                const int hc = j * 4 + (lane & 3);
#pragma unroll
                for (int hrow = 0; hrow < 2; hrow++) {
                    float g = acc[i][j][2 * hrow] + bj[j].x;
                    float l = acc[i][j][2 * hrow + 1] + bj[j].y;
                    g = fminf(g, 7.0f);
                    l = fminf(fmaxf(l, -7.0f), 7.0f);
                    float sg = 1.0f / (1.0f + __expf(-1.702f * g));
                    actb[(size_t)(r1 + 8 * hrow) * 2880 + hc] =
                        __float2half_rn(g * sg * (l + 1.0f));
                }
            }
        }
    } else {
        const float* bb = bias + (size_t)e * NBROWS + n0 + wn * 48;
        float* ob = Dout + row0 * 2880 + n0 + wn * 48;
        float2 bj[NT];
#pragma unroll
        for (int j = 0; j < NT; j++) bj[j] = *(const float2*)(bb + j * 8 + q2);
#pragma unroll
        for (int i = 0; i < 4; i++) {
            const int r1 = wm * 64 + i * 16 + (lane >> 2);
#pragma unroll
            for (int j = 0; j < NT; j++) {
                const int oc = j * 8 + q2;
#pragma unroll
                for (int hrow = 0; hrow < 2; hrow++) {
                    float2 v;
                    v.x = acc[i][j][2 * hrow] + bj[j].x;
                    v.y = acc[i][j][2 * hrow + 1] + bj[j].y;
                    *(float2*)(ob + (size_t)(r1 + 8 * hrow) * 2880 + oc) = v;
                }
            }
        }
    }
}

// ---------------------------------------------------------------------------
extern "C" void kernel_launch(void* const* d_in, const int* in_sizes, int n_in,
                              void* d_out, int out_size) {
    const float* x = (const float*)d_in[0];
    const float* w1 = (const float*)d_in[2];
    const float* b1 = (const float*)d_in[3];
    const float* w2 = (const float*)d_in[4];
    const float* b2 = (const float*)d_in[5];
    float* out = (float*)d_out;

    cudaFuncSetAttribute(moe_mma_kernel<true>,
                         cudaFuncAttributeMaxDynamicSharedMemorySize, SMEM_BYTES);
    cudaFuncSetAttribute(moe_mma_kernel<false>,
                         cudaFuncAttributeMaxDynamicSharedMemorySize, SMEM_BYTES);

    __half *gxh, *gw1h, *gw2h;
    cudaGetSymbolAddress((void**)&gxh, g_xh);
    cudaGetSymbolAddress((void**)&gw1h, g_w1h);
    cudaGetSymbolAddress((void**)&gw2h, g_w2h);

    const size_t nx = (size_t)16384 * 2880 / 4;
    const size_t nw1 = (size_t)8 * 5760 * 2880 / 4;
    const size_t nw2 = (size_t)8 * 2880 * 2880 / 4;
    f32_to_f16_kernel<<<2048, 256>>>((const float4*)x, (__half2*)gxh, nx);
    f32_to_f16_kernel<<<4096, 256>>>((const float4*)w1, (__half2*)gw1h, nw1);
    f32_to_f16_kernel<<<4096, 256>>>((const float4*)w2, (__half2*)gw2h, nw2);

    // GEMM1: 5760/192 = 30 n-tiles; GEMM2: 2880/192 = 15 n-tiles
    moe_mma_kernel<true><<<dim3(30, 128), NTHR, SMEM_BYTES>>>(gw1h, b1, nullptr);
    moe_mma_kernel<false><<<dim3(15, 128), NTHR, SMEM_BYTES>>>(gw2h, b2, out);
}

// round 10
// speedup vs baseline: 1.9797x; 1.0757x over previous
#include <cuda_runtime.h>
#include <cuda_fp16.h>
#include <cstdint>

// ---------------------------------------------------------------------------
// T=16384, D=H=2880, E=8, C=2048, N1=5760. K=2880 both GEMMs.
// fp16 mma.sync m16n8k16, fp32 accumulate. TWO CTAs per SM (4 warps/SMSP)
// to cover barrier/memory bubbles: CTA tile 128x128 (GEMM1) / 128x96 (GEMM2),
// 256 threads, 8 warps (2M x 4N), warp tile 64x(8*NT), 3-stage cp.async,
// 1 barrier/iter, ldmatrix fragments, register-resident swiglu epilogue.
// ---------------------------------------------------------------------------
#define KDIM 2880
#define BM 128
#define BK 64              // halves per k-stage (128 B rows)
#define NSTAGE 3
#define NKITER 45          // 2880/64
#define LDSH 72            // smem pitch in halves (64 + 8 pad) = 144 B
#define A_BYTES (BM * LDSH * 2)  // 18432
#define NTHR 256

__device__ __half g_xh[(size_t)16384 * 2880];
__device__ __half g_w1h[(size_t)8 * 5760 * 2880];
__device__ __half g_w2h[(size_t)8 * 2880 * 2880];
__device__ __half g_acth[(size_t)16384 * 2880];

__device__ __forceinline__ uint32_t s2u(const void* p) {
    uint32_t a;
    asm("{.reg .u64 t; cvta.to.shared.u64 t, %1; cvt.u32.u64 %0, t;}"
        : "=r"(a) : "l"(p));
    return a;
}
__device__ __forceinline__ void cp16(uint32_t dst, const void* src) {
    asm volatile("cp.async.cg.shared.global [%0], [%1], 16;" ::"r"(dst),
                 "l"(src) : "memory");
}
__device__ __forceinline__ void ldsm_x4(uint32_t* r, uint32_t addr) {
    asm volatile(
        "ldmatrix.sync.aligned.m8n8.x4.shared.b16 {%0,%1,%2,%3}, [%4];"
        : "=r"(r[0]), "=r"(r[1]), "=r"(r[2]), "=r"(r[3]) : "r"(addr));
}
__device__ __forceinline__ void ldsm_x2(uint32_t* r, uint32_t addr) {
    asm volatile(
        "ldmatrix.sync.aligned.m8n8.x2.shared.b16 {%0,%1}, [%2];"
        : "=r"(r[0]), "=r"(r[1]) : "r"(addr));
}
__device__ __forceinline__ void mma_f16(float* c, const uint32_t* a,
                                        const uint32_t* b) {
    asm volatile(
        "mma.sync.aligned.m16n8k16.row.col.f32.f16.f16.f32 "
        "{%0,%1,%2,%3}, {%4,%5,%6,%7}, {%8,%9}, {%0,%1,%2,%3};"
        : "+f"(c[0]), "+f"(c[1]), "+f"(c[2]), "+f"(c[3])
        : "r"(a[0]), "r"(a[1]), "r"(a[2]), "r"(a[3]), "r"(b[0]), "r"(b[1]));
}

__global__ void f32_to_f16_kernel(const float4* __restrict__ src,
                                  __half2* __restrict__ dst, size_t n4) {
    size_t i = (size_t)blockIdx.x * blockDim.x + threadIdx.x;
    size_t stride = (size_t)gridDim.x * blockDim.x;
    for (; i < n4; i += stride) {
        float4 v = src[i];
        dst[2 * i] = __floats2half2_rn(v.x, v.y);
        dst[2 * i + 1] = __floats2half2_rn(v.z, v.w);
    }
}

// ---------------------------------------------------------------------------
// NT = n8-subtiles per warp. BN = 32*NT (4 n-warps). NT=4 -> 128, NT=3 -> 96.
// ---------------------------------------------------------------------------
template <bool SWIGLU, int NT>
__global__ __launch_bounds__(NTHR, 2)
void moe_mma_kernel(const __half* __restrict__ Bw, const float* __restrict__ bias,
                    float* __restrict__ Dout) {
    constexpr int BN = 32 * NT;
    constexpr int STAGE_BYTES = (BM + BN) * LDSH * 2;
    constexpr int BCH = NT;  // B cp chunks per thread (A is 4)

    extern __shared__ char smem[];
    const uint32_t smem_u = s2u(smem);

    const int tid = threadIdx.x;
    const int lane = tid & 31;
    const int warp = tid >> 5;
    const int wm = warp & 1;   // 2 warps along M (64 rows)
    const int wn = warp >> 1;  // 4 warps along N (8*NT cols)

    const int bn = blockIdx.x, bm = blockIdx.y;
    const int e = bm >> 4;
    const size_t row0 = (size_t)bm * BM;
    const int n0 = bn * BN;
    const int NBROWS = SWIGLU ? 5760 : 2880;

    const __half* Abase = (SWIGLU ? g_xh : g_acth) + row0 * KDIM;
    const __half* Bbase = Bw + (size_t)e * NBROWS * KDIM + (size_t)n0 * KDIM;

    // copy map: (128+BN) rows x 8 chunks = (4+NT)*256. Branch-free.
    const int crb = tid >> 3;
    const int cc8 = (tid & 7) * 8;
    const __half* Acp = Abase + (size_t)crb * KDIM + cc8;
    const __half* Bcp = Bbase + (size_t)crb * KDIM + cc8;
    const uint32_t sAo = smem_u + (crb * LDSH + cc8) * 2;
    const uint32_t sBo = smem_u + A_BYTES + (crb * LDSH + cc8) * 2;
    const size_t gstep = (size_t)32 * KDIM;
    const uint32_t sstep = 32 * LDSH * 2;

#pragma unroll
    for (int p = 0; p < NSTAGE - 1; p++) {
        const uint32_t sb = p * STAGE_BYTES;
        const int k0 = p * BK;
#pragma unroll
        for (int q = 0; q < 4; q++)
            cp16(sAo + sb + q * sstep, Acp + q * gstep + k0);
#pragma unroll
        for (int q = 0; q < BCH; q++)
            cp16(sBo + sb + q * sstep, Bcp + q * gstep + k0);
        asm volatile("cp.async.commit_group;" ::: "memory");
    }

    float acc[4][NT][4];
#pragma unroll
    for (int i = 0; i < 4; i++)
#pragma unroll
        for (int j = 0; j < NT; j++)
#pragma unroll
            for (int k = 0; k < 4; k++) acc[i][j][k] = 0.0f;

    // ldmatrix lane->address maps (byte offsets within a stage)
    const uint32_t aOff =
        ((wm * 64 + (lane & 15)) * LDSH + (lane >> 4) * 8) * 2;
    // B x4 (n16): lanes 0-7 n0-7@k0, 8-15 n0-7@k8, 16-23 n8-15@k0, 24-31 @k8
    const uint32_t bOff =
        A_BYTES +
        ((wn * (8 * NT) + (lane & 7) + ((lane >> 4) & 1) * 8) * LDSH +
         ((lane >> 3) & 1) * 8) * 2;
    // B x2 (n8, NT odd tail): lanes 0-7 n@k0, 8-15 n@k8
    const uint32_t bOff2 =
        A_BYTES +
        ((wn * (8 * NT) + (NT & ~1) * 8 + (lane & 7)) * LDSH +
         ((lane >> 3) & 1) * 8) * 2;

    for (int it = 0; it < NKITER; it++) {
        asm volatile("cp.async.wait_group 1;" ::: "memory");
        __syncthreads();

        const int kf = it + NSTAGE - 1;
        if (kf < NKITER) {
            const uint32_t sb = (kf % NSTAGE) * STAGE_BYTES;
            const int k0 = kf * BK;
#pragma unroll
            for (int q = 0; q < 4; q++)
                cp16(sAo + sb + q * sstep, Acp + q * gstep + k0);
#pragma unroll
            for (int q = 0; q < BCH; q++)
                cp16(sBo + sb + q * sstep, Bcp + q * gstep + k0);
        }
        asm volatile("cp.async.commit_group;" ::: "memory");

        const uint32_t stg = smem_u + (it % NSTAGE) * STAGE_BYTES;

#pragma unroll
        for (int kk = 0; kk < 4; kk++) {  // 4 k16-steps per BK=64
            const uint32_t stA = stg + aOff + kk * 32;
            const uint32_t stB = stg + bOff + kk * 32;
            uint32_t af[4][4], breg[2 * NT];
#pragma unroll
            for (int i = 0; i < 4; i++)
                ldsm_x4(af[i], stA + i * (16 * LDSH * 2));
#pragma unroll
            for (int p = 0; p < NT / 2; p++)
                ldsm_x4(breg + 4 * p, stB + p * (16 * LDSH * 2));
            if (NT & 1)
                ldsm_x2(breg + 2 * (NT - 1), stg + bOff2 + kk * 32);
#pragma unroll
            for (int i = 0; i < 4; i++)
#pragma unroll
                for (int j = 0; j < NT; j++)
                    mma_f16(acc[i][j], af[i], breg + 2 * j);
        }
    }

    // epilogue (register-resident; pairs (2q,2q+1) in c0/c1 and c2/c3)
    const int q2 = 2 * (lane & 3);
    if (SWIGLU) {
        const float* bb = bias + (size_t)e * NBROWS + n0 + wn * (8 * NT);
        __half* actb = g_acth + row0 * 2880 + (size_t)(n0 >> 1) + wn * (4 * NT);
        float2 bj[NT];
#pragma unroll
        for (int j = 0; j < NT; j++) bj[j] = *(const float2*)(bb + j * 8 + q2);
#pragma unroll
        for (int i = 0; i < 4; i++) {
            const int r1 = wm * 64 + i * 16 + (lane >> 2);
#pragma unroll
            for (int j = 0; j < NT; j++) {
                const int hc = j * 4 + (lane & 3);
#pragma unroll
                for (int hrow = 0; hrow < 2; hrow++) {
                    float g = acc[i][j][2 * hrow] + bj[j].x;
                    float l = acc[i][j][2 * hrow + 1] + bj[j].y;
                    g = fminf(g, 7.0f);
                    l = fminf(fmaxf(l, -7.0f), 7.0f);
                    float sg = 1.0f / (1.0f + __expf(-1.702f * g));
                    actb[(size_t)(r1 + 8 * hrow) * 2880 + hc] =
                        __float2half_rn(g * sg * (l + 1.0f));
                }
            }
        }
    } else {
        const float* bb = bias + (size_t)e * NBROWS + n0 + wn * (8 * NT);
        float* ob = Dout + row0 * 2880 + n0 + wn * (8 * NT);
        float2 bj[NT];
#pragma unroll
        for (int j = 0; j < NT; j++) bj[j] = *(const float2*)(bb + j * 8 + q2);
#pragma unroll
        for (int i = 0; i < 4; i++) {
            const int r1 = wm * 64 + i * 16 + (lane >> 2);
#pragma unroll
            for (int j = 0; j < NT; j++) {
                const int oc = j * 8 + q2;
#pragma unroll
                for (int hrow = 0; hrow < 2; hrow++) {
                    float2 v;
                    v.x = acc[i][j][2 * hrow] + bj[j].x;
                    v.y = acc[i][j][2 * hrow + 1] + bj[j].y;
                    *(float2*)(ob + (size_t)(r1 + 8 * hrow) * 2880 + oc) = v;
                }
            }
        }
    }
}

// ---------------------------------------------------------------------------
extern "C" void kernel_launch(void* const* d_in, const int* in_sizes, int n_in,
                              void* d_out, int out_size) {
    const float* x = (const float*)d_in[0];
    const float* w1 = (const float*)d_in[2];
    const float* b1 = (const float*)d_in[3];
    const float* w2 = (const float*)d_in[4];
    const float* b2 = (const float*)d_in[5];
    float* out = (float*)d_out;

    constexpr int SM1 = NSTAGE * (BM + 128) * LDSH * 2;  // 110592
    constexpr int SM2 = NSTAGE * (BM + 96) * LDSH * 2;   //  96768
    cudaFuncSetAttribute(moe_mma_kernel<true, 4>,
                         cudaFuncAttributeMaxDynamicSharedMemorySize, SM1);
    cudaFuncSetAttribute(moe_mma_kernel<false, 3>,
                         cudaFuncAttributeMaxDynamicSharedMemorySize, SM2);

    __half *gxh, *gw1h, *gw2h;
    cudaGetSymbolAddress((void**)&gxh, g_xh);
    cudaGetSymbolAddress((void**)&gw1h, g_w1h);
    cudaGetSymbolAddress((void**)&gw2h, g_w2h);

    const size_t nx = (size_t)16384 * 2880 / 4;
    const size_t nw1 = (size_t)8 * 5760 * 2880 / 4;
    const size_t nw2 = (size_t)8 * 2880 * 2880 / 4;
    f32_to_f16_kernel<<<2048, 256>>>((const float4*)x, (__half2*)gxh, nx);
    f32_to_f16_kernel<<<4096, 256>>>((const float4*)w1, (__half2*)gw1h, nw1);
    f32_to_f16_kernel<<<4096, 256>>>((const float4*)w2, (__half2*)gw2h, nw2);

    // GEMM1: 5760/128 = 45 n-tiles; GEMM2: 2880/96 = 30 n-tiles
    moe_mma_kernel<true, 4><<<dim3(45, 128), NTHR, SM1>>>(gw1h, b1, nullptr);
    moe_mma_kernel<false, 3><<<dim3(30, 128), NTHR, SM2>>>(gw2h, b2, out);
}